// round 14
// baseline (speedup 1.0000x reference)
#include <cuda_runtime.h>
#include <cstdint>

typedef unsigned int u32;
typedef unsigned long long u64;

// ---------------- BabyBear constants (compile time) ----------------
constexpr u32 PRIME = 2013265921u;
constexpr u32 calc_pinv() {                 // -P^{-1} mod 2^32 (Montgomery, twiddle math only)
    u32 inv = 1u;
    for (int i = 0; i < 5; ++i) inv *= (2u - PRIME * inv);
    return (u32)(0u - inv);
}
constexpr u32 PINV = calc_pinv();
constexpr u64 R1v  = (((u64)1) << 32) % PRIME;
constexpr u32 R2C  = (u32)((R1v * R1v) % PRIME);
constexpr u64 cpow(u64 b, u64 e) {
    u64 r = 1; b %= PRIME;
    while (e) { if (e & 1) r = r * b % PRIME; b = b * b % PRIME; e >>= 1; }
    return r;
}
constexpr u32 OMEGA = (u32)cpow(31, 480);                // GEN^((P-1)/2^22)
constexpr u32 WRAPC = (u32)((((u64)1) << 32) % PRIME);   // 2^32 - 2P
constexpr u32 NWRAP = 0u - WRAPC;                        // -(2^32 mod P) mod 2^32
constexpr u32 SSTRIDE = 2180u;   // per-region shared stride in words (== 4 mod 32)
constexpr int NSLOT = 29;        // seq twiddle slots (phases B,C)
constexpr u32 SEQW = NSLOT * 128;  // 3712

// ---------------- device scratch ----------------
__device__ u32 g_mid[1u << 25];            // 128MB intermediate
__device__ u32 g_twA_M[1024];              // Montgomery: omega_2048^q * R
__device__ u32 g_twB_S[2048];              // standard:  omega^r
__device__ u32 g_seqM[SEQW];               // Montgomery slot-sequenced untwisted twiddles
__device__ u32 g_twist[2048u * SEQW];      // 30MB: standard twisted seq twiddles per k1
__device__ u32 g_twistA[2048u * 16];       // standard twisted phase-A twiddles per k1 (15 used)
__device__ u32 g_cosT1M[64];               // Montgomery: 3^(2048 r) * R
__device__ u32 g_cosCeM[32];               // Montgomery: 3^(131072 e) * R

// ---------------- exact modular helpers (twiddle math only) --------------------
__device__ __forceinline__ u32 mmul(u32 a, u32 b) {      // a*b*R^{-1} mod P (exact)
    u64 t = (u64)a * b;
    u32 m = (u32)t * PINV;
    u32 r = (u32)((t + (u64)m * PRIME) >> 32);
    return r >= PRIME ? r - PRIME : r;
}

// ---------------- int32-wrap emulation, fma/alu pipe-balanced forms ------------
// sign bit via mul.hi (IMAD.HI, fma pipe); fixup via mad.lo (IMAD, fma pipe).
__device__ __forceinline__ u32 wrapred(u32 m) {          // ((int32)m) mod P, m < 2^32
    u32 s, r;
    asm("mul.hi.u32 %0, %1, 2;"         : "=r"(s) : "r"(m));            // m>>31 (fma)
    asm("mad.lo.s32 %0, %1, %2, %3;"    : "=r"(r) : "r"(s), "r"(NWRAP), "r"(m)); // r<2P (fma)
    return min(r, r - PRIME);                                            // alu x2
}
__device__ __forceinline__ u32 wmul(u32 a, u32 b) {      // ((int32)(a*b)) mod P
    u32 m;
    asm("mul.lo.u32 %0, %1, %2;" : "=r"(m) : "r"(a), "r"(b));            // fma
    return wrapred(m);
}
__device__ __forceinline__ u32 wadd(u32 a, u32 b) {      // ((int32)(a+b)) mod P
    return wrapred(a + b);                               // a+b < 2P, same fixup path
}
__device__ __forceinline__ u32 subm(u32 a, u32 b) {      // (a-b) mod P (wrap-free in ref)
    u32 r = a - b, rp;
    asm("mad.lo.s32 %0, %1, 1, %2;" : "=r"(rp) : "r"(r) , "r"(PRIME));   // r+P (fma)
    return min(r, rp);                                                    // alu
}
__device__ __forceinline__ u32 swz(u32 j) { return j + (j >> 4); }

__device__ __forceinline__ u32 ldval(const void* p, u32 i, bool fm) {
    if (fm) return (u32)__ldg((const float*)p + i);
    return (u32)__ldg((const int*)p + i);
}
__device__ __forceinline__ int pick(const void* const* cand, int n, u32 want, bool& fm) {
    u32 fwant = __float_as_uint((float)want);
    for (int i = 0; i < n; ++i) {
        u32 raw = ((const u32*)cand[i])[1];
        if (raw == want)  { fm = false; return i; }
        if (raw == fwant) { fm = true;  return i; }
    }
    fm = false; return 0;
}

#define BFLYW(A, B, W) { u32 _vw = wmul((B), (W)); u32 _a = (A); (B) = subm(_a, _vw); (A) = wadd(_a, _vw); }
#define BFLY1(A, B)    { u32 _v = (B); u32 _a = (A); (B) = subm(_a, _v); (A) = wadd(_a, _v); }
#define TBAR(id) asm volatile("bar.sync %0, 128;" :: "r"(id) : "memory")

// slot -> omega_2048 exponent for thread u (matches consumption order)
__device__ u32 slot_idx(u32 slot, u32 u) {
    u32 plow = u & 15u;
    if (slot == 0)  return plow << 6;                                   // s5
    if (slot < 3)   return (plow | ((slot - 1) << 4)) << 5;             // s6
    if (slot < 7)   return (plow | ((slot - 3) << 4)) << 4;             // s7
    if (slot < 15)  return (plow | ((slot - 7) << 4)) << 3;             // s8
    if (slot < 17)  return (u | ((slot - 15) << 7)) << 2;               // s9
    if (slot < 21)  { u32 g = (slot - 17) >> 1, k = (slot - 17) & 1;
                      return ((u | (g << 7)) | (k << 8)) << 1; }        // s10
    { u32 g = (slot - 21) >> 2, k = (slot - 21) & 3;
      return (u | (g << 7)) | (k << 8); }                               // s11
}
__device__ __forceinline__ int slot_stage(int slot) {
    if (slot == 0)  return 5;
    if (slot < 3)   return 6;
    if (slot < 7)   return 7;
    if (slot < 15)  return 8;
    if (slot < 17)  return 9;
    if (slot < 21)  return 10;
    return 11;
}

// ---------------- setup 1: base tables (twiddles + coset factor tables) --------
__global__ void k_setup(const void* tw0, const void* tw1,
                        const void* c0, const void* c1, const void* c2) {
    const void* tcand[2] = { tw0, tw1 };
    bool fmt, fmc;
    const void* tw = tcand[pick(tcand, 2, OMEGA, fmt)];   // forward twiddles: tw[1] == omega
    const void* ccand[3] = { c0, c1, c2 };
    const void* cos = ccand[pick(ccand, 3, 3u, fmc)];     // coset_powers[1] == 3
    u32 i = blockIdx.x * blockDim.x + threadIdx.x;
    if (i < 2048) {
        g_twB_S[i] = ldval(tw, i, fmt);
    } else if (i < 3072) {
        u32 q = i - 2048;
        g_twA_M[q] = mmul(ldval(tw, q << 11, fmt), R2C);  // omega_2048^q * R
    } else if (i < 3072 + SEQW) {
        u32 s = i - 3072;
        g_seqM[s] = mmul(ldval(tw, slot_idx(s >> 7, s & 127u) << 11, fmt), R2C);
    } else if (i < 3072 + SEQW + 64) {
        u32 r = i - (3072 + SEQW);
        g_cosT1M[r] = mmul(ldval(cos, r << 11, fmc), R2C);   // 3^(2048r) * R
    } else if (i < 3072 + SEQW + 96) {
        u32 e = i - (3072 + SEQW + 64);
        g_cosCeM[e] = mmul(ldval(cos, e << 17, fmc), R2C);   // 3^(131072e) * R
    }
}

// ---------------- setup 2: twisted twiddle tables for every k1 ------------------
__global__ void k_twist() {
    const u32 k1 = blockIdx.x;         // [0,2048)
    const u32 u  = threadIdx.x;        // [0,128)
    u32 base[12];
    #pragma unroll
    for (int s = 1; s <= 11; ++s) {
        u32 E = k1 << (11 - s);        // < 2^21
        base[s] = mmul(__ldg(&g_twA_M[E >> 11]), __ldg(&g_twB_S[E & 2047u]));
    }
    if (u < 15) {                      // phase-A table: s1 k=0; s2 k<2; s3 k<4; s4 k<8
        int s, k;
        if (u == 0)     { s = 1; k = 0; }
        else if (u < 3) { s = 2; k = u - 1; }
        else if (u < 7) { s = 3; k = u - 3; }
        else            { s = 4; k = u - 7; }
        g_twistA[k1 * 16 + u] = mmul(__ldg(&g_twA_M[(u32)k << (11 - s)]), base[s]);
    }
    #pragma unroll
    for (int slot = 0; slot < NSLOT; ++slot)
        g_twist[k1 * SEQW + slot * 128 + u] =
            mmul(__ldg(&g_seqM[slot * 128 + u]), base[slot_stage(slot)]);
}

// ---------------- dual-region 2048-point NTT core (interleaved) ----------------
// W1ONE: untwisted (pass 1) -> all k=0 twiddles are 1: add/sub shortcuts.
template<bool W1ONE>
__device__ __forceinline__ void ntt2048_dual(u32* colA, u32* colB, u32 u, u32 bar,
                                             const u32* __restrict__ twAa,
                                             const u32* __restrict__ twAb,
                                             const u32* __restrict__ twsa,
                                             const u32* __restrict__ twsb) {
    u32 x[16], y[16];
    u32 r7 = __brev(u) >> 25;                          // rev7(u)

    // ---- phase A (stages 1..4): j = 16u+e ; bitrev source = rev4(e)<<7 | rev7(u)
    #pragma unroll
    for (int e = 0; e < 16; ++e) {
        u32 rev4e = ((e & 1) << 3) | ((e & 2) << 1) | ((e & 4) >> 1) | ((e & 8) >> 3);
        u32 a = swz((rev4e << 7) | r7);
        x[e] = colA[a];
        y[e] = colB[a];
    }
    if constexpr (W1ONE) {
        #pragma unroll
        for (int e = 0; e < 16; e += 2) { BFLY1(x[e], x[e + 1]); BFLY1(y[e], y[e + 1]); }
    } else {
        u32 wa = __ldg(&twAa[0]), wb = __ldg(&twAb[0]);
        #pragma unroll
        for (int e = 0; e < 16; e += 2) {
            BFLYW(x[e], x[e + 1], wa);
            BFLYW(y[e], y[e + 1], wb);
        }
    }
    #pragma unroll
    for (int s = 2; s <= 4; ++s) {
        const int h = 1 << (s - 1);
        const int off = h - 1;                         // 1,3,7
        #pragma unroll
        for (int k = 0; k < h; ++k) {
            if (W1ONE && k == 0) {                     // w = 1 (wrap-exact shortcut)
                #pragma unroll
                for (int bq = 0; bq < 16; bq += 2 * h) {
                    BFLY1(x[bq], x[bq + h]);
                    BFLY1(y[bq], y[bq + h]);
                }
            } else {
                u32 wa = __ldg(&twAa[off + k]), wb = __ldg(&twAb[off + k]);
                #pragma unroll
                for (int bq = 0; bq < 16; bq += 2 * h) {
                    BFLYW(x[bq + k], x[bq + k + h], wa);
                    BFLYW(y[bq + k], y[bq + k + h], wb);
                }
            }
        }
    }
    TBAR(bar);
    #pragma unroll
    for (int e = 0; e < 16; ++e) {
        u32 a = swz(16u * u + e);
        colA[a] = x[e];
        colB[a] = y[e];
    }
    TBAR(bar);

    // ---- phase B (stages 5..8): j = (u&15) | ((u>>4)<<8) | (e<<4)
    u32 baseB = (u & 15u) | ((u >> 4) << 8);
    #pragma unroll
    for (int e = 0; e < 16; ++e) {
        u32 a = swz(baseB | ((u32)e << 4));
        x[e] = colA[a];
        y[e] = colB[a];
    }
    {   // stage 5
        u32 wa = __ldg(&twsa[0 * 128 + u]), wb = __ldg(&twsb[0 * 128 + u]);
        #pragma unroll
        for (int bq = 0; bq < 16; bq += 2) {
            BFLYW(x[bq], x[bq + 1], wa);
            BFLYW(y[bq], y[bq + 1], wb);
        }
    }
    #pragma unroll
    for (int k = 0; k < 2; ++k) {                      // stage 6
        u32 wa = __ldg(&twsa[(1 + k) * 128 + u]), wb = __ldg(&twsb[(1 + k) * 128 + u]);
        #pragma unroll
        for (int bq = 0; bq < 16; bq += 4) {
            BFLYW(x[bq + k], x[bq + k + 2], wa);
            BFLYW(y[bq + k], y[bq + k + 2], wb);
        }
    }
    #pragma unroll
    for (int k = 0; k < 4; ++k) {                      // stage 7
        u32 wa = __ldg(&twsa[(3 + k) * 128 + u]), wb = __ldg(&twsb[(3 + k) * 128 + u]);
        #pragma unroll
        for (int bq = 0; bq < 16; bq += 8) {
            BFLYW(x[bq + k], x[bq + k + 4], wa);
            BFLYW(y[bq + k], y[bq + k + 4], wb);
        }
    }
    #pragma unroll
    for (int k = 0; k < 8; ++k) {                      // stage 8
        u32 wa = __ldg(&twsa[(7 + k) * 128 + u]), wb = __ldg(&twsb[(7 + k) * 128 + u]);
        BFLYW(x[k], x[k + 8], wa);
        BFLYW(y[k], y[k + 8], wb);
    }
    #pragma unroll
    for (int e = 0; e < 16; ++e) {
        u32 a = swz(baseB | ((u32)e << 4));
        colA[a] = x[e];
        colB[a] = y[e];
    }
    TBAR(bar);

    // ---- phase C (stages 9..11): j = u | (g<<7) | (e<<8)
    #pragma unroll
    for (int g = 0; g < 2; ++g)
        #pragma unroll
        for (int e = 0; e < 8; ++e) {
            u32 a = swz(u | ((u32)g << 7) | ((u32)e << 8));
            x[g * 8 + e] = colA[a];
            y[g * 8 + e] = colB[a];
        }
    #pragma unroll
    for (int g = 0; g < 2; ++g) {                      // stage 9
        u32 wa = __ldg(&twsa[(15 + g) * 128 + u]), wb = __ldg(&twsb[(15 + g) * 128 + u]);
        #pragma unroll
        for (int bq = 0; bq < 8; bq += 2) {
            BFLYW(x[g * 8 + bq], x[g * 8 + bq + 1], wa);
            BFLYW(y[g * 8 + bq], y[g * 8 + bq + 1], wb);
        }
    }
    #pragma unroll
    for (int g = 0; g < 2; ++g)                        // stage 10
        #pragma unroll
        for (int k = 0; k < 2; ++k) {
            u32 wa = __ldg(&twsa[(17 + 2 * g + k) * 128 + u]);
            u32 wb = __ldg(&twsb[(17 + 2 * g + k) * 128 + u]);
            #pragma unroll
            for (int bq = 0; bq < 8; bq += 4) {
                BFLYW(x[g * 8 + bq + k], x[g * 8 + bq + k + 2], wa);
                BFLYW(y[g * 8 + bq + k], y[g * 8 + bq + k + 2], wb);
            }
        }
    #pragma unroll
    for (int g = 0; g < 2; ++g)                        // stage 11
        #pragma unroll
        for (int k = 0; k < 4; ++k) {
            u32 wa = __ldg(&twsa[(21 + 4 * g + k) * 128 + u]);
            u32 wb = __ldg(&twsb[(21 + 4 * g + k) * 128 + u]);
            BFLYW(x[g * 8 + k], x[g * 8 + k + 4], wa);
            BFLYW(y[g * 8 + k], y[g * 8 + k + 4], wb);
        }
    #pragma unroll
    for (int g = 0; g < 2; ++g)
        #pragma unroll
        for (int e = 0; e < 8; ++e) {
            u32 a = swz(u | ((u32)g << 7) | ((u32)e << 8));
            colA[a] = x[g * 8 + e];
            colB[a] = y[g * 8 + e];
        }
}

// ---------------- pass 1: reference stages 1..11 per column -> g_mid -----------
__global__ void __launch_bounds__(512, 2)
k_pass1(const void* __restrict__ in,
        const void* c0, const void* c1, const void* c2,
        const void* tw0, const void* tw1) {
    extern __shared__ u32 sh[];
    const void* ccand[3] = { c0, c1, c2 };
    bool fm_cos, fm_in;
    const void* coset = ccand[pick(ccand, 3, 3u, fm_cos)];   // coset_powers[1] == 3
    {   const void* tcand[2] = { tw0, tw1 };
        pick(tcand, 2, OMEGA, fm_in);                         // input shares canonical dtype
    }

    const u32 t  = threadIdx.x;
    const u32 b  = blockIdx.y;
    const u32 cb = blockIdx.x * 8u;
    const u32 r  = t >> 3, cc = t & 7u;      // r in [0,64), 8 columns
    const u32 base_in = b << 22;

    // per-thread coset partial: 3^(2048r + cb+cc)  (exact standard form)
    const u32 cpart = mmul(__ldg(&g_cosT1M[r]), ldval(coset, cb + cc, fm_cos));

    #pragma unroll
    for (int e = 0; e < 32; ++e) {
        u32 j1   = r + 64u * (u32)e;
        u32 gidx = j1 * 2048u + cb + cc;
        u32 v = ldval(in, base_in + gidx, fm_in);
        u32 c = mmul(__ldg(&g_cosCeM[e]), cpart);  // 3^gidx exact == coset_powers[gidx]
        v = wmul(v, c);                            // wrapped `input * coset % P`
        sh[cc * SSTRIDE + swz(j1)] = v;
    }
    __syncthreads();

    const u32 T = t >> 7, u = t & 127u;
    ntt2048_dual<true>(sh + T * SSTRIDE, sh + (T + 4u) * SSTRIDE, u, T + 1u,
                       g_twistA, g_twistA, g_twist, g_twist);
    __syncthreads();

    const u32 j2 = cb + cc;
    #pragma unroll
    for (int e = 0; e < 32; ++e) {
        u32 k1 = r + 64u * (u32)e;
        g_mid[base_in | (k1 * 2048u + j2)] = sh[cc * SSTRIDE + swz(k1)];
    }
}

// ---------------- pass 2: reference stages 12..22 per k1 -> d_out (float32) ----
__global__ void __launch_bounds__(512, 2)
k_pass2(float* __restrict__ out) {
    extern __shared__ u32 sh[];
    const u32 t  = threadIdx.x;
    const u32 b  = blockIdx.y;
    const u32 rb = blockIdx.x * 8u;
    const u32 mbase = (b << 22) | (rb * 2048u);

    // vectorized deposit: thread reads 2 x 16 contiguous words (regions T and T+4)
    {
        const u32 tl = t & 127u;
        const u32 dep = 17u * tl;                  // swz(16*tl + m) = 17*tl + m
        #pragma unroll
        for (int i = 0; i < 2; ++i) {
            u32* dst = sh + ((t >> 7) + 4u * (u32)i) * SSTRIDE + dep;
            const uint4* src = (const uint4*)&g_mid[mbase + 16u * t + 8192u * (u32)i];
            #pragma unroll
            for (int q = 0; q < 4; ++q) {
                uint4 v = __ldg(&src[q]);
                dst[4 * q + 0] = v.x; dst[4 * q + 1] = v.y;
                dst[4 * q + 2] = v.z; dst[4 * q + 3] = v.w;
            }
        }
    }
    __syncthreads();

    const u32 T = t >> 7, u = t & 127u;
    const u32 k1a = rb + T, k1b = rb + T + 4u;
    ntt2048_dual<false>(sh + T * SSTRIDE, sh + (T + 4u) * SSTRIDE, u, T + 1u,
                        g_twistA + k1a * 16u, g_twistA + k1b * 16u,
                        g_twist + k1a * SEQW, g_twist + k1b * SEQW);
    __syncthreads();

    const u32 r = t >> 3, cc = t & 7u;
    const u32 k1 = rb + cc;
    const u32 obase = b << 22;
    #pragma unroll
    for (int e = 0; e < 32; ++e) {
        u32 k2 = r + 64u * (u32)e;
        u32 v  = sh[cc * SSTRIDE + swz(k2)];
        out[obase + k1 + (k2 << 11)] = (float)v;   // output buffer is float32
    }
}

// ---------------- launch ----------------
extern "C" void kernel_launch(void* const* d_in, const int* in_sizes, int n_in,
                              void* d_out, int out_size) {
    const void* inp = nullptr;
    const void* tw[2] = { nullptr, nullptr };
    const void* cs[3] = { nullptr, nullptr, nullptr };
    int ntw = 0, ncs = 0;
    for (int i = 0; i < n_in; ++i) {
        long long sz = in_sizes[i];
        if (sz == (1LL << 25)) inp = d_in[i];
        else if (sz == (1LL << 21) && ntw < 2) tw[ntw++] = d_in[i];
        else if (sz == (1LL << 22) && ncs < 3) cs[ncs++] = d_in[i];
    }
    if (!inp)    inp   = d_in[0];
    if (ntw < 2) { tw[0] = d_in[1]; tw[1] = d_in[2]; }
    if (ncs < 3) { cs[0] = d_in[3]; cs[1] = d_in[4]; cs[2] = d_in[5]; }

    const int smem = 8 * SSTRIDE * (int)sizeof(u32);   // 69760 B
    cudaFuncSetAttribute(k_pass1, cudaFuncAttributeMaxDynamicSharedMemorySize, smem);
    cudaFuncSetAttribute(k_pass2, cudaFuncAttributeMaxDynamicSharedMemorySize, smem);

    k_setup<<<27, 256>>>(tw[0], tw[1], cs[0], cs[1], cs[2]);
    k_twist<<<2048, 128>>>();
    dim3 grid(256, 8);
    k_pass1<<<grid, 512, smem>>>(inp, cs[0], cs[1], cs[2], tw[0], tw[1]);
    k_pass2<<<grid, 512, smem>>>((float*)d_out);
}

// round 15
// speedup vs baseline: 1.0655x; 1.0655x over previous
#include <cuda_runtime.h>
#include <cstdint>

typedef unsigned int u32;
typedef unsigned long long u64;

// ---------------- BabyBear constants (compile time) ----------------
constexpr u32 PRIME = 2013265921u;
constexpr u32 calc_pinv() {                 // -P^{-1} mod 2^32 (Montgomery, twiddle math only)
    u32 inv = 1u;
    for (int i = 0; i < 5; ++i) inv *= (2u - PRIME * inv);
    return (u32)(0u - inv);
}
constexpr u32 PINV = calc_pinv();
constexpr u64 R1v  = (((u64)1) << 32) % PRIME;
constexpr u32 R2C  = (u32)((R1v * R1v) % PRIME);
constexpr u64 cpow(u64 b, u64 e) {
    u64 r = 1; b %= PRIME;
    while (e) { if (e & 1) r = r * b % PRIME; b = b * b % PRIME; e >>= 1; }
    return r;
}
constexpr u32 OMEGA = (u32)cpow(31, 480);                // GEN^((P-1)/2^22)
constexpr u32 WRAPC = (u32)((((u64)1) << 32) % PRIME);   // 2^32 - 2P
constexpr u32 SSTRIDE = 2180u;   // per-region shared stride in words (== 4 mod 32)
constexpr int NSLOT = 29;        // seq twiddle slots (phases B,C)
constexpr u32 SEQW = NSLOT * 128;  // 3712

// ---------------- device scratch ----------------
__device__ u32 g_mid[1u << 25];            // 128MB intermediate
__device__ u32 g_twA_M[1024];              // Montgomery: omega_2048^q * R
__device__ u32 g_twB_S[2048];              // standard:  omega^r
__device__ u32 g_seqM[SEQW];               // Montgomery slot-sequenced untwisted twiddles
__device__ u32 g_twist[2048u * SEQW];      // 30MB: standard twisted seq twiddles per k1
__device__ u32 g_twistA[2048u * 16];       // standard twisted phase-A twiddles per k1 (15 used)
__device__ u32 g_cosT1M[64];               // Montgomery: 3^(2048 r) * R
__device__ u32 g_cosCeM[32];               // Montgomery: 3^(131072 e) * R

// ---------------- exact modular helpers (twiddle math only) --------------------
__device__ __forceinline__ u32 mmul(u32 a, u32 b) {      // a*b*R^{-1} mod P (exact)
    u64 t = (u64)a * b;
    u32 m = (u32)t * PINV;
    u32 r = (u32)((t + (u64)m * PRIME) >> 32);
    return r >= PRIME ? r - PRIME : r;
}

// ---------------- int32-wrap emulation (R13 proven minimal forms) --------------
__device__ __forceinline__ u32 wmul(u32 a, u32 b) {      // ((int32)(a*b)) mod P
    u32 m = a * b;                        // low 32 bits, wraps like the reference
    u32 r = m - (m >> 31) * WRAPC;        // sign fixup, r < 2P
    return min(r, r - PRIME);             // conditional subtract via unsigned-min
}
__device__ __forceinline__ u32 wadd(u32 a, u32 b) {      // ((int32)(a+b)) mod P
    u32 t = a + b;
    u32 r = t - (t >> 31) * WRAPC;
    return min(r, r - PRIME);
}
__device__ __forceinline__ u32 subm(u32 a, u32 b) {      // (a-b) mod P (wrap-free in ref)
    u32 r = a - b;
    return min(r, r + PRIME);
}
__device__ __forceinline__ u32 swz(u32 j) { return j + (j >> 4); }

__device__ __forceinline__ u32 ldval(const void* p, u32 i, bool fm) {
    if (fm) return (u32)__ldg((const float*)p + i);
    return (u32)__ldg((const int*)p + i);
}
__device__ __forceinline__ int pick(const void* const* cand, int n, u32 want, bool& fm) {
    u32 fwant = __float_as_uint((float)want);
    for (int i = 0; i < n; ++i) {
        u32 raw = ((const u32*)cand[i])[1];
        if (raw == want)  { fm = false; return i; }
        if (raw == fwant) { fm = true;  return i; }
    }
    fm = false; return 0;
}

#define BFLYW(A, B, W) { u32 _vw = wmul((B), (W)); u32 _a = (A); (B) = subm(_a, _vw); (A) = wadd(_a, _vw); }
#define BFLY1(A, B)    { u32 _v = (B); u32 _a = (A); (B) = subm(_a, _v); (A) = wadd(_a, _v); }
#define TBAR(id) asm volatile("bar.sync %0, 128;" :: "r"(id) : "memory")

// slot -> omega_2048 exponent for thread u (matches consumption order)
__device__ u32 slot_idx(u32 slot, u32 u) {
    u32 plow = u & 15u;
    if (slot == 0)  return plow << 6;                                   // s5
    if (slot < 3)   return (plow | ((slot - 1) << 4)) << 5;             // s6
    if (slot < 7)   return (plow | ((slot - 3) << 4)) << 4;             // s7
    if (slot < 15)  return (plow | ((slot - 7) << 4)) << 3;             // s8
    if (slot < 17)  return (u | ((slot - 15) << 7)) << 2;               // s9
    if (slot < 21)  { u32 g = (slot - 17) >> 1, k = (slot - 17) & 1;
                      return ((u | (g << 7)) | (k << 8)) << 1; }        // s10
    { u32 g = (slot - 21) >> 2, k = (slot - 21) & 3;
      return (u | (g << 7)) | (k << 8); }                               // s11
}
__device__ __forceinline__ int slot_stage(int slot) {
    if (slot == 0)  return 5;
    if (slot < 3)   return 6;
    if (slot < 7)   return 7;
    if (slot < 15)  return 8;
    if (slot < 17)  return 9;
    if (slot < 21)  return 10;
    return 11;
}

// ---------------- setup 1: base tables (twiddles + coset factor tables) --------
__global__ void k_setup(const void* tw0, const void* tw1,
                        const void* c0, const void* c1, const void* c2) {
    const void* tcand[2] = { tw0, tw1 };
    bool fmt, fmc;
    const void* tw = tcand[pick(tcand, 2, OMEGA, fmt)];   // forward twiddles: tw[1] == omega
    const void* ccand[3] = { c0, c1, c2 };
    const void* cos = ccand[pick(ccand, 3, 3u, fmc)];     // coset_powers[1] == 3
    u32 i = blockIdx.x * blockDim.x + threadIdx.x;
    if (i < 2048) {
        g_twB_S[i] = ldval(tw, i, fmt);
    } else if (i < 3072) {
        u32 q = i - 2048;
        g_twA_M[q] = mmul(ldval(tw, q << 11, fmt), R2C);  // omega_2048^q * R
    } else if (i < 3072 + SEQW) {
        u32 s = i - 3072;
        g_seqM[s] = mmul(ldval(tw, slot_idx(s >> 7, s & 127u) << 11, fmt), R2C);
    } else if (i < 3072 + SEQW + 64) {
        u32 r = i - (3072 + SEQW);
        g_cosT1M[r] = mmul(ldval(cos, r << 11, fmc), R2C);   // 3^(2048r) * R
    } else if (i < 3072 + SEQW + 96) {
        u32 e = i - (3072 + SEQW + 64);
        g_cosCeM[e] = mmul(ldval(cos, e << 17, fmc), R2C);   // 3^(131072e) * R
    }
}

// ---------------- setup 2: twisted twiddle tables for every k1 ------------------
__global__ void k_twist() {
    const u32 k1 = blockIdx.x;         // [0,2048)
    const u32 u  = threadIdx.x;        // [0,128)
    u32 base[12];
    #pragma unroll
    for (int s = 1; s <= 11; ++s) {
        u32 E = k1 << (11 - s);        // < 2^21
        base[s] = mmul(__ldg(&g_twA_M[E >> 11]), __ldg(&g_twB_S[E & 2047u]));
    }
    if (u < 15) {                      // phase-A table: s1 k=0; s2 k<2; s3 k<4; s4 k<8
        int s, k;
        if (u == 0)     { s = 1; k = 0; }
        else if (u < 3) { s = 2; k = u - 1; }
        else if (u < 7) { s = 3; k = u - 3; }
        else            { s = 4; k = u - 7; }
        g_twistA[k1 * 16 + u] = mmul(__ldg(&g_twA_M[(u32)k << (11 - s)]), base[s]);
    }
    #pragma unroll
    for (int slot = 0; slot < NSLOT; ++slot)
        g_twist[k1 * SEQW + slot * 128 + u] =
            mmul(__ldg(&g_seqM[slot * 128 + u]), base[slot_stage(slot)]);
}

// ---------------- dual-region 2048-point NTT core (interleaved) ----------------
// W1ONE: untwisted (pass 1) -> all k=0 twiddles are 1: add/sub shortcuts.
template<bool W1ONE>
__device__ __forceinline__ void ntt2048_dual(u32* colA, u32* colB, u32 u, u32 bar,
                                             const u32* __restrict__ twAa,
                                             const u32* __restrict__ twAb,
                                             const u32* __restrict__ twsa,
                                             const u32* __restrict__ twsb) {
    u32 x[16], y[16];
    u32 r7 = __brev(u) >> 25;                          // rev7(u)

    // ---- phase A (stages 1..4): j = 16u+e ; bitrev source = rev4(e)<<7 | rev7(u)
    #pragma unroll
    for (int e = 0; e < 16; ++e) {
        u32 rev4e = ((e & 1) << 3) | ((e & 2) << 1) | ((e & 4) >> 1) | ((e & 8) >> 3);
        u32 a = swz((rev4e << 7) | r7);
        x[e] = colA[a];
        y[e] = colB[a];
    }
    if constexpr (W1ONE) {
        #pragma unroll
        for (int e = 0; e < 16; e += 2) { BFLY1(x[e], x[e + 1]); BFLY1(y[e], y[e + 1]); }
    } else {
        u32 wa = __ldg(&twAa[0]), wb = __ldg(&twAb[0]);
        #pragma unroll
        for (int e = 0; e < 16; e += 2) {
            BFLYW(x[e], x[e + 1], wa);
            BFLYW(y[e], y[e + 1], wb);
        }
    }
    #pragma unroll
    for (int s = 2; s <= 4; ++s) {
        const int h = 1 << (s - 1);
        const int off = h - 1;                         // 1,3,7
        #pragma unroll
        for (int k = 0; k < h; ++k) {
            if (W1ONE && k == 0) {                     // w = 1 (wrap-exact shortcut)
                #pragma unroll
                for (int bq = 0; bq < 16; bq += 2 * h) {
                    BFLY1(x[bq], x[bq + h]);
                    BFLY1(y[bq], y[bq + h]);
                }
            } else {
                u32 wa = __ldg(&twAa[off + k]), wb = __ldg(&twAb[off + k]);
                #pragma unroll
                for (int bq = 0; bq < 16; bq += 2 * h) {
                    BFLYW(x[bq + k], x[bq + k + h], wa);
                    BFLYW(y[bq + k], y[bq + k + h], wb);
                }
            }
        }
    }
    TBAR(bar);
    #pragma unroll
    for (int e = 0; e < 16; ++e) {
        u32 a = swz(16u * u + e);
        colA[a] = x[e];
        colB[a] = y[e];
    }
    TBAR(bar);

    // ---- phase B (stages 5..8): j = (u&15) | ((u>>4)<<8) | (e<<4)
    u32 baseB = (u & 15u) | ((u >> 4) << 8);
    #pragma unroll
    for (int e = 0; e < 16; ++e) {
        u32 a = swz(baseB | ((u32)e << 4));
        x[e] = colA[a];
        y[e] = colB[a];
    }
    {   // stage 5
        u32 wa = __ldg(&twsa[0 * 128 + u]), wb = __ldg(&twsb[0 * 128 + u]);
        #pragma unroll
        for (int bq = 0; bq < 16; bq += 2) {
            BFLYW(x[bq], x[bq + 1], wa);
            BFLYW(y[bq], y[bq + 1], wb);
        }
    }
    #pragma unroll
    for (int k = 0; k < 2; ++k) {                      // stage 6
        u32 wa = __ldg(&twsa[(1 + k) * 128 + u]), wb = __ldg(&twsb[(1 + k) * 128 + u]);
        #pragma unroll
        for (int bq = 0; bq < 16; bq += 4) {
            BFLYW(x[bq + k], x[bq + k + 2], wa);
            BFLYW(y[bq + k], y[bq + k + 2], wb);
        }
    }
    #pragma unroll
    for (int k = 0; k < 4; ++k) {                      // stage 7
        u32 wa = __ldg(&twsa[(3 + k) * 128 + u]), wb = __ldg(&twsb[(3 + k) * 128 + u]);
        #pragma unroll
        for (int bq = 0; bq < 16; bq += 8) {
            BFLYW(x[bq + k], x[bq + k + 4], wa);
            BFLYW(y[bq + k], y[bq + k + 4], wb);
        }
    }
    #pragma unroll
    for (int k = 0; k < 8; ++k) {                      // stage 8
        u32 wa = __ldg(&twsa[(7 + k) * 128 + u]), wb = __ldg(&twsb[(7 + k) * 128 + u]);
        BFLYW(x[k], x[k + 8], wa);
        BFLYW(y[k], y[k + 8], wb);
    }
    #pragma unroll
    for (int e = 0; e < 16; ++e) {
        u32 a = swz(baseB | ((u32)e << 4));
        colA[a] = x[e];
        colB[a] = y[e];
    }
    TBAR(bar);

    // ---- phase C (stages 9..11): j = u | (g<<7) | (e<<8)
    #pragma unroll
    for (int g = 0; g < 2; ++g)
        #pragma unroll
        for (int e = 0; e < 8; ++e) {
            u32 a = swz(u | ((u32)g << 7) | ((u32)e << 8));
            x[g * 8 + e] = colA[a];
            y[g * 8 + e] = colB[a];
        }
    #pragma unroll
    for (int g = 0; g < 2; ++g) {                      // stage 9
        u32 wa = __ldg(&twsa[(15 + g) * 128 + u]), wb = __ldg(&twsb[(15 + g) * 128 + u]);
        #pragma unroll
        for (int bq = 0; bq < 8; bq += 2) {
            BFLYW(x[g * 8 + bq], x[g * 8 + bq + 1], wa);
            BFLYW(y[g * 8 + bq], y[g * 8 + bq + 1], wb);
        }
    }
    #pragma unroll
    for (int g = 0; g < 2; ++g)                        // stage 10
        #pragma unroll
        for (int k = 0; k < 2; ++k) {
            u32 wa = __ldg(&twsa[(17 + 2 * g + k) * 128 + u]);
            u32 wb = __ldg(&twsb[(17 + 2 * g + k) * 128 + u]);
            #pragma unroll
            for (int bq = 0; bq < 8; bq += 4) {
                BFLYW(x[g * 8 + bq + k], x[g * 8 + bq + k + 2], wa);
                BFLYW(y[g * 8 + bq + k], y[g * 8 + bq + k + 2], wb);
            }
        }
    #pragma unroll
    for (int g = 0; g < 2; ++g)                        // stage 11
        #pragma unroll
        for (int k = 0; k < 4; ++k) {
            u32 wa = __ldg(&twsa[(21 + 4 * g + k) * 128 + u]);
            u32 wb = __ldg(&twsb[(21 + 4 * g + k) * 128 + u]);
            BFLYW(x[g * 8 + k], x[g * 8 + k + 4], wa);
            BFLYW(y[g * 8 + k], y[g * 8 + k + 4], wb);
        }
    #pragma unroll
    for (int g = 0; g < 2; ++g)
        #pragma unroll
        for (int e = 0; e < 8; ++e) {
            u32 a = swz(u | ((u32)g << 7) | ((u32)e << 8));
            colA[a] = x[g * 8 + e];
            colB[a] = y[g * 8 + e];
        }
}

// ---------------- pass 1: reference stages 1..11 per column -> g_mid -----------
__global__ void __launch_bounds__(512, 2)
k_pass1(const void* __restrict__ in,
        const void* c0, const void* c1, const void* c2,
        const void* tw0, const void* tw1) {
    extern __shared__ u32 sh[];
    const void* ccand[3] = { c0, c1, c2 };
    bool fm_cos, fm_in;
    const void* coset = ccand[pick(ccand, 3, 3u, fm_cos)];   // coset_powers[1] == 3
    {   const void* tcand[2] = { tw0, tw1 };
        pick(tcand, 2, OMEGA, fm_in);                         // input shares canonical dtype
    }

    const u32 t  = threadIdx.x;
    const u32 b  = blockIdx.y;
    const u32 cb = blockIdx.x * 8u;
    const u32 r  = t >> 3, cc = t & 7u;      // r in [0,64), 8 columns
    const u32 base_in = b << 22;

    // per-thread coset partial: 3^(2048r + cb+cc)  (exact standard form)
    const u32 cpart = mmul(__ldg(&g_cosT1M[r]), ldval(coset, cb + cc, fm_cos));

    #pragma unroll
    for (int e = 0; e < 32; ++e) {
        u32 j1   = r + 64u * (u32)e;
        u32 gidx = j1 * 2048u + cb + cc;
        u32 v = ldval(in, base_in + gidx, fm_in);
        u32 c = mmul(__ldg(&g_cosCeM[e]), cpart);  // 3^gidx exact == coset_powers[gidx]
        v = wmul(v, c);                            // wrapped `input * coset % P`
        sh[cc * SSTRIDE + swz(j1)] = v;
    }
    __syncthreads();

    const u32 T = t >> 7, u = t & 127u;
    ntt2048_dual<true>(sh + T * SSTRIDE, sh + (T + 4u) * SSTRIDE, u, T + 1u,
                       g_twistA, g_twistA, g_twist, g_twist);
    __syncthreads();

    const u32 j2 = cb + cc;
    #pragma unroll
    for (int e = 0; e < 32; ++e) {
        u32 k1 = r + 64u * (u32)e;
        g_mid[base_in | (k1 * 2048u + j2)] = sh[cc * SSTRIDE + swz(k1)];
    }
}

// ---------------- pass 2: reference stages 12..22 per k1 -> d_out (float32) ----
__global__ void __launch_bounds__(512, 2)
k_pass2(float* __restrict__ out) {
    extern __shared__ u32 sh[];
    const u32 t  = threadIdx.x;
    const u32 b  = blockIdx.y;
    const u32 rb = blockIdx.x * 8u;
    const u32 mbase = (b << 22) | (rb * 2048u);

    // vectorized deposit: thread reads 2 x 16 contiguous words (regions T and T+4)
    {
        const u32 tl = t & 127u;
        const u32 dep = 17u * tl;                  // swz(16*tl + m) = 17*tl + m
        #pragma unroll
        for (int i = 0; i < 2; ++i) {
            u32* dst = sh + ((t >> 7) + 4u * (u32)i) * SSTRIDE + dep;
            const uint4* src = (const uint4*)&g_mid[mbase + 16u * t + 8192u * (u32)i];
            #pragma unroll
            for (int q = 0; q < 4; ++q) {
                uint4 v = __ldg(&src[q]);
                dst[4 * q + 0] = v.x; dst[4 * q + 1] = v.y;
                dst[4 * q + 2] = v.z; dst[4 * q + 3] = v.w;
            }
        }
    }
    __syncthreads();

    const u32 T = t >> 7, u = t & 127u;
    const u32 k1a = rb + T, k1b = rb + T + 4u;
    ntt2048_dual<false>(sh + T * SSTRIDE, sh + (T + 4u) * SSTRIDE, u, T + 1u,
                        g_twistA + k1a * 16u, g_twistA + k1b * 16u,
                        g_twist + k1a * SEQW, g_twist + k1b * SEQW);
    __syncthreads();

    const u32 r = t >> 3, cc = t & 7u;
    const u32 k1 = rb + cc;
    const u32 obase = b << 22;
    #pragma unroll
    for (int e = 0; e < 32; ++e) {
        u32 k2 = r + 64u * (u32)e;
        u32 v  = sh[cc * SSTRIDE + swz(k2)];
        out[obase + k1 + (k2 << 11)] = (float)v;   // output buffer is float32
    }
}

// ---------------- launch ----------------
extern "C" void kernel_launch(void* const* d_in, const int* in_sizes, int n_in,
                              void* d_out, int out_size) {
    const void* inp = nullptr;
    const void* tw[2] = { nullptr, nullptr };
    const void* cs[3] = { nullptr, nullptr, nullptr };
    int ntw = 0, ncs = 0;
    for (int i = 0; i < n_in; ++i) {
        long long sz = in_sizes[i];
        if (sz == (1LL << 25)) inp = d_in[i];
        else if (sz == (1LL << 21) && ntw < 2) tw[ntw++] = d_in[i];
        else if (sz == (1LL << 22) && ncs < 3) cs[ncs++] = d_in[i];
    }
    if (!inp)    inp   = d_in[0];
    if (ntw < 2) { tw[0] = d_in[1]; tw[1] = d_in[2]; }
    if (ncs < 3) { cs[0] = d_in[3]; cs[1] = d_in[4]; cs[2] = d_in[5]; }

    const int smem = 8 * SSTRIDE * (int)sizeof(u32);   // 69760 B
    cudaFuncSetAttribute(k_pass1, cudaFuncAttributeMaxDynamicSharedMemorySize, smem);
    cudaFuncSetAttribute(k_pass2, cudaFuncAttributeMaxDynamicSharedMemorySize, smem);

    k_setup<<<27, 256>>>(tw[0], tw[1], cs[0], cs[1], cs[2]);
    k_twist<<<2048, 128>>>();
    dim3 grid(256, 8);
    k_pass1<<<grid, 512, smem>>>(inp, cs[0], cs[1], cs[2], tw[0], tw[1]);
    k_pass2<<<grid, 512, smem>>>((float*)d_out);
}